// round 3
// baseline (speedup 1.0000x reference)
#include <cuda_runtime.h>
#include <cuda_bf16.h>

// Problem constants (fixed by the reference's setup_inputs)
#define N_NODES 100000
#define E_EDGES 1600000

// Scratch: __device__ globals (no cudaMalloc allowed)
__device__ int   g_deg[N_NODES];
__device__ float g_inflow[2][N_NODES];

// ---------------------------------------------------------------------------
// K0: zero degree counters, both inflow buffers, and out[0] (cost accumulator)
// ---------------------------------------------------------------------------
__global__ void k_zero(float* __restrict__ out0) {
    int i = blockIdx.x * blockDim.x + threadIdx.x;
    if (i < N_NODES) {
        g_deg[i] = 0;
        g_inflow[0][i] = 0.0f;
        g_inflow[1][i] = 0.0f;
    }
    if (i == 0) *out0 = 0.0f;
}

// ---------------------------------------------------------------------------
// K1: out-degree histogram over original edges
// ---------------------------------------------------------------------------
__global__ void k_count(const int* __restrict__ src, int E) {
    int i = blockIdx.x * blockDim.x + threadIdx.x;
    if (i < E) atomicAdd(&g_deg[__ldg(&src[i])], 1);
}

// ---------------------------------------------------------------------------
// K2: fw[e] = 1/(deg[src]+1e-9)  (== 1/deg exactly in f32 for deg>=1),
//     flow[e] = fw[e].  flow/fw are only 4B-aligned (out+1) -> scalar stores.
// ---------------------------------------------------------------------------
__global__ void k_init(const int* __restrict__ src,
                       float* __restrict__ flow,
                       float* __restrict__ fw, int E) {
    int i = blockIdx.x * blockDim.x + threadIdx.x;
    if (i < E) {
        float den = (float)g_deg[__ldg(&src[i])] + 1e-9f;
        float f = 1.0f / den;       // precise div to match reference bits
        fw[i]   = f;
        flow[i] = f;
    }
}

// ---------------------------------------------------------------------------
// K3: inflow[buf][dst[e]] += flow[e].  2 edges/thread; dst via int2 (input
// arrays are harness-aligned), flow via scalar 4B loads (out+1 alignment).
// ---------------------------------------------------------------------------
__global__ void k_scatter(const int* __restrict__ dst,
                          const float* __restrict__ flow, int E, int buf) {
    int i2 = blockIdx.x * blockDim.x + threadIdx.x;   // pair index
    int i  = i2 * 2;
    if (i + 1 < E) {
        int2  d  = *(const int2*)(dst + i);
        float f0 = __ldg(&flow[i]);
        float f1 = __ldg(&flow[i + 1]);
        atomicAdd(&g_inflow[buf][d.x], f0);
        atomicAdd(&g_inflow[buf][d.y], f1);
    } else if (i < E) {
        atomicAdd(&g_inflow[buf][__ldg(&dst[i])], __ldg(&flow[i]));
    }
}

// ---------------------------------------------------------------------------
// K4: flow[e] = fw[e] * relu(inflow[buf][src[e]] - d0[src[e]])
//     Also zeroes the OTHER inflow buffer (dead at this point in the graph)
//     so the next scatter starts clean without an extra launch.
// ---------------------------------------------------------------------------
__global__ void k_apply(const int* __restrict__ src,
                        const float* __restrict__ fw,
                        const float* __restrict__ d0,
                        float* __restrict__ flow, int E, int buf) {
    int i2 = blockIdx.x * blockDim.x + threadIdx.x;
    int i  = i2 * 2;
    const float* __restrict__ infl = g_inflow[buf];
    if (i + 1 < E) {
        int2  s  = *(const int2*)(src + i);
        float w0 = __ldg(&fw[i]);
        float w1 = __ldg(&fw[i + 1]);
        float a0 = fmaxf(__ldg(&infl[s.x]) - __ldg(&d0[s.x]), 0.0f);
        float a1 = fmaxf(__ldg(&infl[s.y]) - __ldg(&d0[s.y]), 0.0f);
        flow[i]     = w0 * a0;
        flow[i + 1] = w1 * a1;
    } else if (i < E) {
        int s = __ldg(&src[i]);
        float a = fmaxf(__ldg(&infl[s]) - __ldg(&d0[s]), 0.0f);
        flow[i] = __ldg(&fw[i]) * a;
    }
    // Zero the other buffer with just the first N_NODES threads' worth of work.
    if (i2 < N_NODES) g_inflow[buf ^ 1][i2] = 0.0f;
}

// ---------------------------------------------------------------------------
// K5: flow_cost = sum(flow^2)   (COST_CONST = 1.0)
// ---------------------------------------------------------------------------
__global__ void k_cost(const float* __restrict__ flow, float* __restrict__ out0, int E) {
    __shared__ float warp_part[32];
    float acc = 0.0f;
    for (int i = blockIdx.x * blockDim.x + threadIdx.x; i < E;
         i += gridDim.x * blockDim.x) {
        float v = __ldg(&flow[i]);
        acc += v * v;
    }
    #pragma unroll
    for (int o = 16; o > 0; o >>= 1)
        acc += __shfl_down_sync(0xFFFFFFFF, acc, o);
    int lane = threadIdx.x & 31;
    int wid  = threadIdx.x >> 5;
    if (lane == 0) warp_part[wid] = acc;
    __syncthreads();
    if (wid == 0) {
        int nw = (blockDim.x + 31) >> 5;
        acc = (lane < nw) ? warp_part[lane] : 0.0f;
        #pragma unroll
        for (int o = 16; o > 0; o >>= 1)
            acc += __shfl_down_sync(0xFFFFFFFF, acc, o);
        if (lane == 0) atomicAdd(out0, acc);
    }
}

// ---------------------------------------------------------------------------
// Launch. Inputs (metadata order): demands, node_embeddings, edge_src,
// edge_dst, W_enc, b_enc, W_gat, a_src_w, a_dst_w, b_gat, W_gx, W_gh, b_g,
// W_dec, b_dec.  Output layout: [flow_cost(1), flow(E), fw(E)].
//
// Math note (why the GNN is skipped): scores = pred[edge_src], so within
// every softmax segment (keyed by edge_src) all scores are equal. Then
// e - m == 0 exactly, exp == 1.0 exactly, den == out_degree exactly, and
// den + 1e-9 rounds back to den in f32 for deg >= 1. Hence
// fw[e] = 1/out_degree(src[e]) bitwise — independent of the entire GNN.
// The three outputs depend only on fw, demands, edge_src, edge_dst.
// ---------------------------------------------------------------------------
extern "C" void kernel_launch(void* const* d_in, const int* in_sizes, int n_in,
                              void* d_out, int out_size) {
    const float* demands = (const float*)d_in[0];   // N x 1
    const int*   src     = (const int*)  d_in[2];   // E
    const int*   dst     = (const int*)  d_in[3];   // E
    const int E = in_sizes[2];

    float* out  = (float*)d_out;
    float* flow = out + 1;       // E floats (only 4B aligned!)
    float* fw   = out + 1 + E;   // E floats (only 4B aligned!)

    const int T   = 256;
    const int BE  = (E + T - 1) / T;            // 1 edge / thread
    const int BE2 = (E / 2 + T) / T;            // 2 edges / thread (covers tail)
    const int BN  = (N_NODES + T - 1) / T;

    k_zero<<<BN, T>>>(out);
    k_count<<<BE, T>>>(src, E);
    k_init<<<BE, T>>>(src, flow, fw, E);

    for (int it = 0; it < 10; ++it) {
        int buf = it & 1;
        k_scatter<<<BE2, T>>>(dst, flow, E, buf);
        k_apply<<<BE2, T>>>(src, fw, demands, flow, E, buf);
    }

    k_cost<<<1024, 256>>>(flow, out, E);
}

// round 4
// speedup vs baseline: 1.1521x; 1.1521x over previous
#include <cuda_runtime.h>
#include <cuda_bf16.h>

// Problem constants (fixed by the reference's setup_inputs)
#define N_NODES  100000
#define E_EDGES  1600000
#define FLOW_ITERS 10

// Persistent-kernel geometry: must be co-resident for the software grid barrier.
#define GRID 592
#define TPB  256
#define TTOT (GRID * TPB)                      // 151,552 threads
#define EPT_FULL (E_EDGES / TTOT)              // 10 full strides
#define EPT (EPT_FULL + 1)                     // 11 (last stride partial)
#define E_TAIL (E_EDGES - EPT_FULL * TTOT)     // 84,480 edges in last stride

// Scratch (__device__ globals; no cudaMalloc allowed)
__device__ int      g_deg[N_NODES];
__device__ float    g_inflow[N_NODES];
__device__ float    g_a[N_NODES];
__device__ unsigned g_count;                   // barrier arrival counter
__device__ unsigned g_gen;                     // barrier generation

// Software grid barrier (all GRID blocks co-resident by construction).
__device__ __forceinline__ void gbar() {
    __syncthreads();
    if (threadIdx.x == 0) {
        unsigned old = *(volatile unsigned*)&g_gen;   // read BEFORE arriving
        __threadfence();
        if (atomicAdd(&g_count, 1u) == GRID - 1) {
            g_count = 0;
            __threadfence();
            atomicAdd(&g_gen, 1u);                    // release
        } else {
            while (*(volatile unsigned*)&g_gen == old) { __nanosleep(64); }
        }
        __threadfence();                              // acquire
    }
    __syncthreads();
}

// ---------------------------------------------------------------------------
// Persistent fused kernel. Edge payload (src, dst, fw) lives in registers for
// the entire 10-iteration flow loop. Per iteration per edge: one L2 gather of
// a[src] + one REDG into inflow[dst]. a/inflow/deg cross SMs between barriers
// -> L1-bypassing __ldcg/__stcg (L1 is not coherent vs other SMs' atomics).
// ---------------------------------------------------------------------------
__global__ void __launch_bounds__(TPB, 4)
k_persist(const int* __restrict__ src_g, const int* __restrict__ dst_g,
          const float* __restrict__ d0, float* __restrict__ out)
{
    const int tid = blockIdx.x * TPB + threadIdx.x;
    float* __restrict__ flow_out = out + 1;
    float* __restrict__ fw_out   = out + 1 + E_EDGES;

    const bool tail_ok = (tid < E_TAIL);

    // Load edge indices into registers (coalesced strided layout).
    int esrc[EPT], edst[EPT];
    float efw[EPT];
#pragma unroll
    for (int k = 0; k < EPT_FULL; k++) {
        esrc[k] = __ldg(src_g + tid + k * TTOT);
        edst[k] = __ldg(dst_g + tid + k * TTOT);
    }
    esrc[EPT_FULL] = tail_ok ? __ldg(src_g + tid + EPT_FULL * TTOT) : 0;
    edst[EPT_FULL] = tail_ok ? __ldg(dst_g + tid + EPT_FULL * TTOT) : 0;

    // Prologue: zero deg, inflow, cost accumulator.
    if (tid < N_NODES) { g_deg[tid] = 0; __stcg(&g_inflow[tid], 0.0f); }
    if (tid == 0) out[0] = 0.0f;
    gbar();

    // Out-degree histogram of src.
#pragma unroll
    for (int k = 0; k < EPT_FULL; k++) atomicAdd(&g_deg[esrc[k]], 1);
    if (tail_ok) atomicAdd(&g_deg[esrc[EPT_FULL]], 1);
    gbar();

    // fw[e] = 1/(deg[src]+1e-9) : identical bits to reference seg-softmax
    // (all scores in a segment are equal -> exp==1, den==deg exactly).
#pragma unroll
    for (int k = 0; k < EPT; k++) {
        bool ok = (k < EPT_FULL) || tail_ok;
        float f = 0.0f;
        if (ok) {
            float den = (float)__ldcg(&g_deg[esrc[k]]) + 1e-9f;
            f = 1.0f / den;
            fw_out[tid + k * TTOT] = f;
        }
        efw[k] = f;
    }

    // Flow loop, entirely in node space. a_v = relu(inflow_v - d0),
    // inflow_{v+1}[dst] += fw * a_v[src]. flow_0 = fw -> first scatter is fw.
    for (int it = 0; it < FLOW_ITERS; ++it) {
        if (it == 0) {
#pragma unroll
            for (int k = 0; k < EPT_FULL; k++)
                atomicAdd(&g_inflow[edst[k]], efw[k]);
            if (tail_ok) atomicAdd(&g_inflow[edst[EPT_FULL]], efw[EPT_FULL]);
        } else {
#pragma unroll
            for (int k = 0; k < EPT_FULL; k++) {
                float v = efw[k] * __ldcg(&g_a[esrc[k]]);
                atomicAdd(&g_inflow[edst[k]], v);
            }
            if (tail_ok) {
                float v = efw[EPT_FULL] * __ldcg(&g_a[esrc[EPT_FULL]]);
                atomicAdd(&g_inflow[edst[EPT_FULL]], v);
            }
        }
        gbar();
        // Node pass: a = relu(inflow - d0); re-zero inflow for next round.
        if (tid < N_NODES) {
            float v = __ldcg(&g_inflow[tid]) - __ldg(&d0[tid]);
            __stcg(&g_a[tid], fmaxf(v, 0.0f));
            __stcg(&g_inflow[tid], 0.0f);
        }
        gbar();
    }

    // Epilogue: materialize flow = fw * a_final[src], accumulate sum(flow^2).
    float acc = 0.0f;
#pragma unroll
    for (int k = 0; k < EPT_FULL; k++) {
        float fl = efw[k] * __ldcg(&g_a[esrc[k]]);
        flow_out[tid + k * TTOT] = fl;
        acc += fl * fl;
    }
    if (tail_ok) {
        float fl = efw[EPT_FULL] * __ldcg(&g_a[esrc[EPT_FULL]]);
        flow_out[tid + EPT_FULL * TTOT] = fl;
        acc += fl * fl;
    }

    // Block-reduce cost, one atomicAdd per block.
    __shared__ float warp_part[TPB / 32];
#pragma unroll
    for (int o = 16; o > 0; o >>= 1)
        acc += __shfl_down_sync(0xFFFFFFFF, acc, o);
    int lane = threadIdx.x & 31, wid = threadIdx.x >> 5;
    if (lane == 0) warp_part[wid] = acc;
    __syncthreads();
    if (wid == 0) {
        acc = (lane < TPB / 32) ? warp_part[lane] : 0.0f;
#pragma unroll
        for (int o = 16; o > 0; o >>= 1)
            acc += __shfl_down_sync(0xFFFFFFFF, acc, o);
        if (lane == 0) atomicAdd(out, acc);
    }
}

// ======================= Fallback path (proven R3 kernels) ==================
__device__ float g_inflow2[2][N_NODES];

__global__ void k_zero(float* __restrict__ out0) {
    int i = blockIdx.x * blockDim.x + threadIdx.x;
    if (i < N_NODES) {
        g_deg[i] = 0;
        g_inflow2[0][i] = 0.0f;
        g_inflow2[1][i] = 0.0f;
    }
    if (i == 0) *out0 = 0.0f;
}

__global__ void k_count(const int* __restrict__ src, int E) {
    int i = blockIdx.x * blockDim.x + threadIdx.x;
    if (i < E) atomicAdd(&g_deg[__ldg(&src[i])], 1);
}

__global__ void k_init(const int* __restrict__ src,
                       float* __restrict__ flow,
                       float* __restrict__ fw, int E) {
    int i = blockIdx.x * blockDim.x + threadIdx.x;
    if (i < E) {
        float den = (float)g_deg[__ldg(&src[i])] + 1e-9f;
        float f = 1.0f / den;
        fw[i]   = f;
        flow[i] = f;
    }
}

__global__ void k_scatter(const int* __restrict__ dst,
                          const float* __restrict__ flow, int E, int buf) {
    int i2 = blockIdx.x * blockDim.x + threadIdx.x;
    int i  = i2 * 2;
    if (i + 1 < E) {
        int2  d  = *(const int2*)(dst + i);
        float f0 = __ldg(&flow[i]);
        float f1 = __ldg(&flow[i + 1]);
        atomicAdd(&g_inflow2[buf][d.x], f0);
        atomicAdd(&g_inflow2[buf][d.y], f1);
    } else if (i < E) {
        atomicAdd(&g_inflow2[buf][__ldg(&dst[i])], __ldg(&flow[i]));
    }
}

__global__ void k_apply(const int* __restrict__ src,
                        const float* __restrict__ fw,
                        const float* __restrict__ d0,
                        float* __restrict__ flow, int E, int buf) {
    int i2 = blockIdx.x * blockDim.x + threadIdx.x;
    int i  = i2 * 2;
    const float* __restrict__ infl = g_inflow2[buf];
    if (i + 1 < E) {
        int2  s  = *(const int2*)(src + i);
        float w0 = __ldg(&fw[i]);
        float w1 = __ldg(&fw[i + 1]);
        float a0 = fmaxf(__ldg(&infl[s.x]) - __ldg(&d0[s.x]), 0.0f);
        float a1 = fmaxf(__ldg(&infl[s.y]) - __ldg(&d0[s.y]), 0.0f);
        flow[i]     = w0 * a0;
        flow[i + 1] = w1 * a1;
    } else if (i < E) {
        int s = __ldg(&src[i]);
        float a = fmaxf(__ldg(&infl[s]) - __ldg(&d0[s]), 0.0f);
        flow[i] = __ldg(&fw[i]) * a;
    }
    if (i2 < N_NODES) g_inflow2[buf ^ 1][i2] = 0.0f;
}

__global__ void k_cost(const float* __restrict__ flow, float* __restrict__ out0, int E) {
    __shared__ float warp_part[32];
    float acc = 0.0f;
    for (int i = blockIdx.x * blockDim.x + threadIdx.x; i < E;
         i += gridDim.x * blockDim.x) {
        float v = __ldg(&flow[i]);
        acc += v * v;
    }
    #pragma unroll
    for (int o = 16; o > 0; o >>= 1)
        acc += __shfl_down_sync(0xFFFFFFFF, acc, o);
    int lane = threadIdx.x & 31;
    int wid  = threadIdx.x >> 5;
    if (lane == 0) warp_part[wid] = acc;
    __syncthreads();
    if (wid == 0) {
        int nw = (blockDim.x + 31) >> 5;
        acc = (lane < nw) ? warp_part[lane] : 0.0f;
        #pragma unroll
        for (int o = 16; o > 0; o >>= 1)
            acc += __shfl_down_sync(0xFFFFFFFF, acc, o);
        if (lane == 0) atomicAdd(out0, acc);
    }
}

// ---------------------------------------------------------------------------
// Launch. Inputs: demands, node_embeddings, edge_src, edge_dst, [weights...].
// Output layout: [flow_cost(1), flow(E), fw(E)]. The GNN is provably dead
// code w.r.t. the outputs (uniform per-segment softmax scores).
// ---------------------------------------------------------------------------
extern "C" void kernel_launch(void* const* d_in, const int* in_sizes, int n_in,
                              void* d_out, int out_size) {
    const float* demands = (const float*)d_in[0];   // N x 1
    const int*   src     = (const int*)  d_in[2];   // E
    const int*   dst     = (const int*)  d_in[3];   // E
    const int E = in_sizes[2];
    const int Nn = in_sizes[0];

    float* out  = (float*)d_out;
    float* flow = out + 1;       // E floats (only 4B aligned!)
    float* fw   = out + 1 + E;   // E floats (only 4B aligned!)

    // Can the persistent kernel's GRID blocks be fully co-resident?
    bool use_persist = (E == E_EDGES && Nn == N_NODES);
    if (use_persist) {
        int dev = 0, sms = 0, occ = 0;
        cudaGetDevice(&dev);
        cudaDeviceGetAttribute(&sms, cudaDevAttrMultiProcessorCount, dev);
        cudaOccupancyMaxActiveBlocksPerMultiprocessor(&occ, k_persist, TPB, 0);
        if ((long long)occ * sms < GRID) use_persist = false;
    }

    if (use_persist) {
        k_persist<<<GRID, TPB>>>(src, dst, demands, out);
        return;
    }

    // Fallback: proven multi-kernel path.
    const int T   = 256;
    const int BE  = (E + T - 1) / T;
    const int BE2 = (E / 2 + T) / T;
    const int BN  = (N_NODES + T - 1) / T;

    k_zero<<<BN, T>>>(out);
    k_count<<<BE, T>>>(src, E);
    k_init<<<BE, T>>>(src, flow, fw, E);
    for (int it = 0; it < FLOW_ITERS; ++it) {
        int buf = it & 1;
        k_scatter<<<BE2, T>>>(dst, flow, E, buf);
        k_apply<<<BE2, T>>>(src, fw, demands, flow, E, buf);
    }
    k_cost<<<1024, 256>>>(flow, out, E);
}

// round 5
// speedup vs baseline: 1.4234x; 1.2355x over previous
#include <cuda_runtime.h>
#include <cuda_bf16.h>

// Problem constants (fixed by the reference's setup_inputs)
#define N_NODES  100000
#define E_EDGES  1600000
#define FLOW_ITERS 10

// Persistent-kernel geometry: must be co-resident for the software grid barrier.
#define GRID 592
#define TPB  256
#define TTOT (GRID * TPB)                      // 151,552 threads
#define EPT_FULL (E_EDGES / TTOT)              // 10 full strides
#define EPT (EPT_FULL + 1)                     // 11 (last stride partial)
#define E_TAIL (E_EDGES - EPT_FULL * TTOT)     // 84,480 edges in last stride

// Scratch (__device__ globals; no cudaMalloc allowed)
__device__ int      g_deg[N_NODES];
__device__ float4   g_node[3][N_NODES];        // {inflow, d0, invdeg, pad}
__device__ unsigned g_count;                   // barrier arrival counter
__device__ unsigned g_gen;                     // barrier generation

// Software grid barrier (all GRID blocks co-resident by construction).
__device__ __forceinline__ void gbar() {
    __syncthreads();
    if (threadIdx.x == 0) {
        unsigned old = *(volatile unsigned*)&g_gen;   // read BEFORE arriving
        __threadfence();
        if (atomicAdd(&g_count, 1u) == GRID - 1) {
            g_count = 0;
            __threadfence();
            atomicAdd(&g_gen, 1u);                    // release
        } else {
            while (*(volatile unsigned*)&g_gen == old) { __nanosleep(64); }
        }
        __threadfence();                              // acquire
    }
    __syncthreads();
}

// ---------------------------------------------------------------------------
// Persistent fused kernel. Edge indices live in registers for all 10
// iterations. Per edge per iteration: ONE float4 L2 gather (inflow, d0,
// invdeg in one LDG.128 -> compute v = invdeg*relu(inflow-d0) locally) and
// ONE REDG scatter. 3-buffer rotation gives one grid barrier per iteration.
// ---------------------------------------------------------------------------
__global__ void __launch_bounds__(TPB, 4)
k_persist(const int* __restrict__ src_g, const int* __restrict__ dst_g,
          const float* __restrict__ d0, float* __restrict__ out)
{
    const int tid = blockIdx.x * TPB + threadIdx.x;
    float* __restrict__ flow_out = out + 1;
    float* __restrict__ fw_out   = out + 1 + E_EDGES;

    const bool tail_ok = (tid < E_TAIL);

    // Load edge indices into registers (coalesced strided layout).
    int esrc[EPT], edst[EPT];
#pragma unroll
    for (int k = 0; k < EPT_FULL; k++) {
        esrc[k] = __ldg(src_g + tid + k * TTOT);
        edst[k] = __ldg(dst_g + tid + k * TTOT);
    }
    esrc[EPT_FULL] = tail_ok ? __ldg(src_g + tid + EPT_FULL * TTOT) : 0;
    edst[EPT_FULL] = tail_ok ? __ldg(dst_g + tid + EPT_FULL * TTOT) : 0;

    // Prologue 1: zero deg + cost accumulator.
    if (tid < N_NODES) g_deg[tid] = 0;
    if (tid == 0) out[0] = 0.0f;
    gbar();

    // Prologue 2: out-degree histogram of src.
#pragma unroll
    for (int k = 0; k < EPT_FULL; k++) atomicAdd(&g_deg[esrc[k]], 1);
    if (tail_ok) atomicAdd(&g_deg[esrc[EPT_FULL]], 1);
    gbar();

    // Prologue 3: node records in all 3 buffers.
    // invdeg = 1/(deg+1e-9): bitwise identical to the reference seg-softmax
    // (all scores per segment equal -> exp==1, den==deg exactly).
    if (tid < N_NODES) {
        float den = (float)__ldcg(&g_deg[tid]) + 1e-9f;
        float4 nd;
        nd.x = 0.0f;
        nd.y = __ldg(&d0[tid]);
        nd.z = 1.0f / den;
        nd.w = 0.0f;
        __stcg(&g_node[0][tid], nd);
        __stcg(&g_node[1][tid], nd);
        __stcg(&g_node[2][tid], nd);
    }
    gbar();

    // Iter 0 (peeled): flow_0 = fw = invdeg[src]. Scatter into buf0 and emit
    // the fw output. Gather invdeg from buf2 (idle this iteration).
    {
        const float4* __restrict__ nr = g_node[2];
        float4* __restrict__ nw = g_node[0];
#pragma unroll
        for (int k = 0; k < EPT_FULL; k++) {
            float f = __ldcg(&nr[esrc[k]]).z;
            fw_out[tid + k * TTOT] = f;
            atomicAdd(&nw[edst[k]].x, f);
        }
        if (tail_ok) {
            float f = __ldcg(&nr[esrc[EPT_FULL]]).z;
            fw_out[tid + EPT_FULL * TTOT] = f;
            atomicAdd(&nw[edst[EPT_FULL]].x, f);
        }
        gbar();
    }

    // Iters 1..9: read buf[(it-1)%3], write buf[it%3], zero buf[(it+1)%3].x.
    for (int it = 1; it < FLOW_ITERS; ++it) {
        const float4* __restrict__ nr = g_node[(it - 1) % 3];
        float4* __restrict__ nw = g_node[it % 3];
        float4* __restrict__ nz = g_node[(it + 1) % 3];

#pragma unroll
        for (int k = 0; k < EPT_FULL; k++) {
            float4 nd = __ldcg(&nr[esrc[k]]);
            float v = nd.z * fmaxf(nd.x - nd.y, 0.0f);   // fw * relu(inflow-d0)
            atomicAdd(&nw[edst[k]].x, v);
        }
        if (tail_ok) {
            float4 nd = __ldcg(&nr[esrc[EPT_FULL]]);
            float v = nd.z * fmaxf(nd.x - nd.y, 0.0f);
            atomicAdd(&nw[edst[EPT_FULL]].x, v);
        }
        // Zero next write-buffer's inflow field (last read two barriers ago).
        if (tid < N_NODES && it + 1 < FLOW_ITERS)
            __stcg(&nz[tid].x, 0.0f);
        gbar();
    }

    // Epilogue: final buffer holds inflow_10 (buf[(FLOW_ITERS-1)%3] = buf0).
    // flow = invdeg[src]*relu(inflow[src]-d0[src]); accumulate sum(flow^2).
    const float4* __restrict__ nf = g_node[(FLOW_ITERS - 1) % 3];
    float acc = 0.0f;
#pragma unroll
    for (int k = 0; k < EPT_FULL; k++) {
        float4 nd = __ldcg(&nf[esrc[k]]);
        float fl = nd.z * fmaxf(nd.x - nd.y, 0.0f);
        flow_out[tid + k * TTOT] = fl;
        acc += fl * fl;
    }
    if (tail_ok) {
        float4 nd = __ldcg(&nf[esrc[EPT_FULL]]);
        float fl = nd.z * fmaxf(nd.x - nd.y, 0.0f);
        flow_out[tid + EPT_FULL * TTOT] = fl;
        acc += fl * fl;
    }

    // Block-reduce cost, one atomicAdd per block.
    __shared__ float warp_part[TPB / 32];
#pragma unroll
    for (int o = 16; o > 0; o >>= 1)
        acc += __shfl_down_sync(0xFFFFFFFF, acc, o);
    int lane = threadIdx.x & 31, wid = threadIdx.x >> 5;
    if (lane == 0) warp_part[wid] = acc;
    __syncthreads();
    if (wid == 0) {
        acc = (lane < TPB / 32) ? warp_part[lane] : 0.0f;
#pragma unroll
        for (int o = 16; o > 0; o >>= 1)
            acc += __shfl_down_sync(0xFFFFFFFF, acc, o);
        if (lane == 0) atomicAdd(out, acc);
    }
}

// ======================= Fallback path (proven R3 kernels) ==================
__device__ float g_inflow2[2][N_NODES];

__global__ void k_zero(float* __restrict__ out0) {
    int i = blockIdx.x * blockDim.x + threadIdx.x;
    if (i < N_NODES) {
        g_deg[i] = 0;
        g_inflow2[0][i] = 0.0f;
        g_inflow2[1][i] = 0.0f;
    }
    if (i == 0) *out0 = 0.0f;
}

__global__ void k_count(const int* __restrict__ src, int E) {
    int i = blockIdx.x * blockDim.x + threadIdx.x;
    if (i < E) atomicAdd(&g_deg[__ldg(&src[i])], 1);
}

__global__ void k_init(const int* __restrict__ src,
                       float* __restrict__ flow,
                       float* __restrict__ fw, int E) {
    int i = blockIdx.x * blockDim.x + threadIdx.x;
    if (i < E) {
        float den = (float)g_deg[__ldg(&src[i])] + 1e-9f;
        float f = 1.0f / den;
        fw[i]   = f;
        flow[i] = f;
    }
}

__global__ void k_scatter(const int* __restrict__ dst,
                          const float* __restrict__ flow, int E, int buf) {
    int i2 = blockIdx.x * blockDim.x + threadIdx.x;
    int i  = i2 * 2;
    if (i + 1 < E) {
        int2  d  = *(const int2*)(dst + i);
        float f0 = __ldg(&flow[i]);
        float f1 = __ldg(&flow[i + 1]);
        atomicAdd(&g_inflow2[buf][d.x], f0);
        atomicAdd(&g_inflow2[buf][d.y], f1);
    } else if (i < E) {
        atomicAdd(&g_inflow2[buf][__ldg(&dst[i])], __ldg(&flow[i]));
    }
}

__global__ void k_apply(const int* __restrict__ src,
                        const float* __restrict__ fw,
                        const float* __restrict__ d0,
                        float* __restrict__ flow, int E, int buf) {
    int i2 = blockIdx.x * blockDim.x + threadIdx.x;
    int i  = i2 * 2;
    const float* __restrict__ infl = g_inflow2[buf];
    if (i + 1 < E) {
        int2  s  = *(const int2*)(src + i);
        float w0 = __ldg(&fw[i]);
        float w1 = __ldg(&fw[i + 1]);
        float a0 = fmaxf(__ldg(&infl[s.x]) - __ldg(&d0[s.x]), 0.0f);
        float a1 = fmaxf(__ldg(&infl[s.y]) - __ldg(&d0[s.y]), 0.0f);
        flow[i]     = w0 * a0;
        flow[i + 1] = w1 * a1;
    } else if (i < E) {
        int s = __ldg(&src[i]);
        float a = fmaxf(__ldg(&infl[s]) - __ldg(&d0[s]), 0.0f);
        flow[i] = __ldg(&fw[i]) * a;
    }
    if (i2 < N_NODES) g_inflow2[buf ^ 1][i2] = 0.0f;
}

__global__ void k_cost(const float* __restrict__ flow, float* __restrict__ out0, int E) {
    __shared__ float warp_part[32];
    float acc = 0.0f;
    for (int i = blockIdx.x * blockDim.x + threadIdx.x; i < E;
         i += gridDim.x * blockDim.x) {
        float v = __ldg(&flow[i]);
        acc += v * v;
    }
    #pragma unroll
    for (int o = 16; o > 0; o >>= 1)
        acc += __shfl_down_sync(0xFFFFFFFF, acc, o);
    int lane = threadIdx.x & 31;
    int wid  = threadIdx.x >> 5;
    if (lane == 0) warp_part[wid] = acc;
    __syncthreads();
    if (wid == 0) {
        int nw = (blockDim.x + 31) >> 5;
        acc = (lane < nw) ? warp_part[lane] : 0.0f;
        #pragma unroll
        for (int o = 16; o > 0; o >>= 1)
            acc += __shfl_down_sync(0xFFFFFFFF, acc, o);
        if (lane == 0) atomicAdd(out0, acc);
    }
}

// ---------------------------------------------------------------------------
// Launch. Inputs: demands, node_embeddings, edge_src, edge_dst, [weights...].
// Output layout: [flow_cost(1), flow(E), fw(E)]. The GNN is provably dead
// code w.r.t. the outputs (uniform per-segment softmax scores).
// ---------------------------------------------------------------------------
extern "C" void kernel_launch(void* const* d_in, const int* in_sizes, int n_in,
                              void* d_out, int out_size) {
    const float* demands = (const float*)d_in[0];   // N x 1
    const int*   src     = (const int*)  d_in[2];   // E
    const int*   dst     = (const int*)  d_in[3];   // E
    const int E = in_sizes[2];
    const int Nn = in_sizes[0];

    float* out  = (float*)d_out;
    float* flow = out + 1;       // E floats (only 4B aligned!)
    float* fw   = out + 1 + E;   // E floats (only 4B aligned!)

    // Can the persistent kernel's GRID blocks be fully co-resident?
    bool use_persist = (E == E_EDGES && Nn == N_NODES);
    if (use_persist) {
        int dev = 0, sms = 0, occ = 0;
        cudaGetDevice(&dev);
        cudaDeviceGetAttribute(&sms, cudaDevAttrMultiProcessorCount, dev);
        cudaOccupancyMaxActiveBlocksPerMultiprocessor(&occ, k_persist, TPB, 0);
        if ((long long)occ * sms < GRID) use_persist = false;
    }

    if (use_persist) {
        k_persist<<<GRID, TPB>>>(src, dst, demands, out);
        return;
    }

    // Fallback: proven multi-kernel path.
    const int T   = 256;
    const int BE  = (E + T - 1) / T;
    const int BE2 = (E / 2 + T) / T;
    const int BN  = (N_NODES + T - 1) / T;

    k_zero<<<BN, T>>>(out);
    k_count<<<BE, T>>>(src, E);
    k_init<<<BE, T>>>(src, flow, fw, E);
    for (int it = 0; it < FLOW_ITERS; ++it) {
        int buf = it & 1;
        k_scatter<<<BE2, T>>>(dst, flow, E, buf);
        k_apply<<<BE2, T>>>(src, fw, demands, flow, E, buf);
    }
    k_cost<<<1024, 256>>>(flow, out, E);
}